// round 1
// baseline (speedup 1.0000x reference)
#include <cuda_runtime.h>
#include <math.h>

#define B_  2
#define S_  2048
#define D_  1024
#define H_  16
#define DK_ 64
#define MROWS (B_*S_)      // 4096

// ---------------- scratch (allocation-free: __device__ globals) -------------
__device__ float g_Q[B_*S_*D_];
__device__ float g_K[B_*S_*D_];
__device__ float g_V[B_*S_*D_];
__device__ float g_ctx[B_*S_*D_];
__device__ float g_vsum[B_*H_*DK_];

// ---------------- classic 128x128x8 fp32 SGEMM ------------------------------
// C[M,N] = A[M,K] @ W[K,N] (+ bias).  M=4096, N=1024, K=1024 (all multiples).
template<bool ADD_BIAS>
__global__ void __launch_bounds__(256) sgemm128(const float* __restrict__ A,
                                                const float* __restrict__ Bm,
                                                const float* __restrict__ bias,
                                                float* __restrict__ C) {
    const int K = 1024, N = 1024;
    __shared__ float As[8][128];
    __shared__ float Bs[8][128];
    const int tid = threadIdx.x;
    const int tx = tid & 15;           // 0..15 (N dir)
    const int ty = tid >> 4;           // 0..15 (M dir)
    const int rowBase = blockIdx.y * 128;
    const int colBase = blockIdx.x * 128;

    float acc[8][8] = {};

    const int aRow = tid >> 1;         // 0..127
    const int aCol = (tid & 1) * 4;    // 0 / 4
    const int bRow = tid >> 5;         // 0..7
    const int bCol = (tid & 31) * 4;   // 0..124

    const float* Ap = A  + (size_t)(rowBase + aRow) * K + aCol;
    const float* Bp = Bm + (size_t)bRow * N + colBase + bCol;

    for (int k0 = 0; k0 < K; k0 += 8) {
        float4 a4 = *(const float4*)(Ap + k0);
        float4 b4 = *(const float4*)(Bp + (size_t)k0 * N);
        As[aCol+0][aRow] = a4.x;
        As[aCol+1][aRow] = a4.y;
        As[aCol+2][aRow] = a4.z;
        As[aCol+3][aRow] = a4.w;
        *(float4*)&Bs[bRow][bCol] = b4;
        __syncthreads();
        #pragma unroll
        for (int kk = 0; kk < 8; kk++) {
            float ar[8], br[8];
            *(float4*)(ar)   = *(const float4*)&As[kk][ty*8];
            *(float4*)(ar+4) = *(const float4*)&As[kk][ty*8+4];
            *(float4*)(br)   = *(const float4*)&Bs[kk][tx*8];
            *(float4*)(br+4) = *(const float4*)&Bs[kk][tx*8+4];
            #pragma unroll
            for (int i = 0; i < 8; i++)
                #pragma unroll
                for (int j = 0; j < 8; j++)
                    acc[i][j] = fmaf(ar[i], br[j], acc[i][j]);
        }
        __syncthreads();
    }

    #pragma unroll
    for (int i = 0; i < 8; i++) {
        const int r = rowBase + ty*8 + i;
        #pragma unroll
        for (int j = 0; j < 8; j += 4) {
            const int c = colBase + tx*8 + j;
            float4 v;
            v.x = acc[i][j+0]; v.y = acc[i][j+1];
            v.z = acc[i][j+2]; v.w = acc[i][j+3];
            if (ADD_BIAS) {
                v.x += bias[c+0]; v.y += bias[c+1];
                v.z += bias[c+2]; v.w += bias[c+3];
            }
            *(float4*)&C[(size_t)r * N + c] = v;
        }
    }
}

// ---------------- per-(b,h) V row-sum (for fully-masked rows) ---------------
__global__ void vsum_kernel() {
    __shared__ float red[256];
    const int bh = blockIdx.x;                 // 0..31
    const int b  = bh / H_, h = bh % H_;
    const int dk = threadIdx.x & 63;
    const int chunk = threadIdx.x >> 6;        // 0..3
    const float* Vg = g_V + (size_t)b * S_ * D_ + h * DK_ + dk;
    float s = 0.f;
    for (int i = chunk * 512; i < (chunk + 1) * 512; i++)
        s += Vg[(size_t)i * D_];
    red[threadIdx.x] = s;
    __syncthreads();
    if (threadIdx.x < 64) {
        float t = red[threadIdx.x] + red[threadIdx.x + 64]
                + red[threadIdx.x + 128] + red[threadIdx.x + 192];
        g_vsum[bh * DK_ + threadIdx.x] = t;
    }
}

// ---------------- flash attention: 64x64 tiles, online softmax --------------
#define FBM  64
#define FBN  64
#define FSTR 65

__device__ __forceinline__ float rmax16(float v) {
    v = fmaxf(v, __shfl_xor_sync(0xffffffffu, v, 1));
    v = fmaxf(v, __shfl_xor_sync(0xffffffffu, v, 2));
    v = fmaxf(v, __shfl_xor_sync(0xffffffffu, v, 4));
    v = fmaxf(v, __shfl_xor_sync(0xffffffffu, v, 8));
    return v;
}
__device__ __forceinline__ float rsum16(float v) {
    v += __shfl_xor_sync(0xffffffffu, v, 1);
    v += __shfl_xor_sync(0xffffffffu, v, 2);
    v += __shfl_xor_sync(0xffffffffu, v, 4);
    v += __shfl_xor_sync(0xffffffffu, v, 8);
    return v;
}

__global__ void __launch_bounds__(256) flash_kernel(const int* __restrict__ kpm) {
    extern __shared__ float sm[];
    float* Qs   = sm;                    // 64 x 65
    float* Ks   = Qs + 64 * FSTR;
    float* Vs   = Ks + 64 * FSTR;
    float* Ps   = Vs + 64 * FSTR;
    float* pads = Ps + 64 * FSTR;        // 64: 0=valid key, 1=padded

    const int tid = threadIdx.x;
    const int tx  = tid & 15;            // k / dk direction
    const int ty  = tid >> 4;            // q direction
    const int qblk = blockIdx.x;         // 0..31
    const int bh   = blockIdx.y;         // 0..31
    const int b = bh / H_, h = bh % H_;

    const float* Qg = g_Q + ((size_t)b * S_ + qblk * FBM) * D_ + h * DK_;
    const float* Kg = g_K + (size_t)b * S_ * D_ + h * DK_;
    const float* Vg = g_V + (size_t)b * S_ * D_ + h * DK_;

    // load Q tile (64 rows x 64 cols)
    {
        const int r = tid >> 2;
        const int c = (tid & 3) * 16;
        const float* src = Qg + (size_t)r * D_ + c;
        float* dst = Qs + r * FSTR + c;
        #pragma unroll
        for (int u = 0; u < 16; u++) dst[u] = src[u];
    }

    float m_r[4], l_r[4], o_acc[4][4];
    #pragma unroll
    for (int i = 0; i < 4; i++) {
        m_r[i] = -INFINITY; l_r[i] = 0.f;
        #pragma unroll
        for (int c = 0; c < 4; c++) o_acc[i][c] = 0.f;
    }

    const int nkt = qblk + 1;            // causal: k-tiles 0..qblk
    const int qrow0 = qblk * FBM + 4 * ty;

    for (int kt = 0; kt < nkt; kt++) {
        __syncthreads();                 // prior P@V done reading Ks/Vs
        {
            const int r = tid >> 2;
            const int c = (tid & 3) * 16;
            const float* ks = Kg + (size_t)(kt * FBN + r) * D_ + c;
            const float* vs = Vg + (size_t)(kt * FBN + r) * D_ + c;
            float* kd = Ks + r * FSTR + c;
            float* vd = Vs + r * FSTR + c;
            #pragma unroll
            for (int u = 0; u < 16; u++) { kd[u] = ks[u]; vd[u] = vs[u]; }
        }
        if (tid < 64) pads[tid] = kpm[b * S_ + kt * FBN + tid] ? 1.f : 0.f;
        __syncthreads();

        // scores: S = Q @ K^T
        float s[4][4] = {};
        #pragma unroll 8
        for (int d = 0; d < 64; d++) {
            float qr[4], kr[4];
            #pragma unroll
            for (int i = 0; i < 4; i++) qr[i] = Qs[(4*ty+i)*FSTR + d];
            #pragma unroll
            for (int j = 0; j < 4; j++) kr[j] = Ks[(4*tx+j)*FSTR + d];
            #pragma unroll
            for (int i = 0; i < 4; i++)
                #pragma unroll
                for (int j = 0; j < 4; j++)
                    s[i][j] = fmaf(qr[i], kr[j], s[i][j]);
        }

        // mask + scale
        const int kcol0 = kt * FBN + 4 * tx;
        float padj[4];
        #pragma unroll
        for (int j = 0; j < 4; j++) padj[j] = pads[4*tx + j];
        #pragma unroll
        for (int i = 0; i < 4; i++)
            #pragma unroll
            for (int j = 0; j < 4; j++) {
                bool valid = (kcol0 + j <= qrow0 + i) && (padj[j] == 0.f);
                s[i][j] = valid ? s[i][j] * 0.125f : -INFINITY;
            }

        // online softmax per row
        #pragma unroll
        for (int i = 0; i < 4; i++) {
            float mt = fmaxf(fmaxf(s[i][0], s[i][1]), fmaxf(s[i][2], s[i][3]));
            mt = rmax16(mt);
            const float mn = fmaxf(m_r[i], mt);
            float p[4], psum;
            if (mn == -INFINITY) {
                p[0] = p[1] = p[2] = p[3] = 0.f;
                psum = 0.f;
            } else {
                const float alpha = __expf(m_r[i] - mn);   // exp(-inf)=0 ok
                #pragma unroll
                for (int j = 0; j < 4; j++)
                    p[j] = (s[i][j] == -INFINITY) ? 0.f : __expf(s[i][j] - mn);
                psum = (p[0] + p[1]) + (p[2] + p[3]);
                l_r[i] *= alpha;
                #pragma unroll
                for (int c = 0; c < 4; c++) o_acc[i][c] *= alpha;
            }
            psum = rsum16(psum);
            m_r[i]  = mn;
            l_r[i] += psum;
            #pragma unroll
            for (int j = 0; j < 4; j++)
                Ps[(4*ty+i)*FSTR + 4*tx + j] = p[j];
        }
        __syncthreads();

        // O += P @ V
        #pragma unroll 8
        for (int kk = 0; kk < 64; kk++) {
            float vr[4];
            #pragma unroll
            for (int c = 0; c < 4; c++) vr[c] = Vs[kk * FSTR + 4*tx + c];
            #pragma unroll
            for (int i = 0; i < 4; i++) {
                const float pv = Ps[(4*ty+i)*FSTR + kk];
                #pragma unroll
                for (int c = 0; c < 4; c++)
                    o_acc[i][c] = fmaf(pv, vr[c], o_acc[i][c]);
            }
        }
    }

    // epilogue: normalize; fully-masked rows -> mean over ALL S of V
    const float invS = 1.0f / (float)S_;
    #pragma unroll
    for (int i = 0; i < 4; i++) {
        const bool dead = (m_r[i] == -INFINITY);
        const float inv_l = dead ? 0.f : 1.0f / l_r[i];
        const int q = qrow0 + i;
        float* outp = g_ctx + ((size_t)b * S_ + q) * D_ + h * DK_ + 4 * tx;
        #pragma unroll
        for (int c = 0; c < 4; c++) {
            float val = dead ? g_vsum[bh * DK_ + 4*tx + c] * invS
                             : o_acc[i][c] * inv_l;
            outp[c] = val;
        }
    }
}

// ---------------- launch ------------------------------------------------------
extern "C" void kernel_launch(void* const* d_in, const int* in_sizes, int n_in,
                              void* d_out, int out_size) {
    const float* x   = (const float*)d_in[0];
    // d_in[1] = additive causal mask [S,S] — structure known, not read
    const int*   kpm = (const int*)d_in[2];
    const float* Wq  = (const float*)d_in[3];
    const float* Wk  = (const float*)d_in[4];
    const float* Wv  = (const float*)d_in[5];
    const float* Wo  = (const float*)d_in[6];
    const float* bo  = (const float*)d_in[7];
    float* out = (float*)d_out;

    float *Qp, *Kp, *Vp, *Cp;
    cudaGetSymbolAddress((void**)&Qp, g_Q);
    cudaGetSymbolAddress((void**)&Kp, g_K);
    cudaGetSymbolAddress((void**)&Vp, g_V);
    cudaGetSymbolAddress((void**)&Cp, g_ctx);

    dim3 gg(1024 / 128, MROWS / 128);   // (8, 32)
    sgemm128<false><<<gg, 256>>>(x, Wq, nullptr, Qp);
    sgemm128<false><<<gg, 256>>>(x, Wk, nullptr, Kp);
    sgemm128<false><<<gg, 256>>>(x, Wv, nullptr, Vp);

    vsum_kernel<<<B_ * H_, 256>>>();

    const int smem = (4 * 64 * FSTR + 64) * (int)sizeof(float);   // 66816 B
    cudaFuncSetAttribute(flash_kernel, cudaFuncAttributeMaxDynamicSharedMemorySize, smem);
    dim3 fg(S_ / FBM, B_ * H_);         // (32, 32)
    flash_kernel<<<fg, 256, smem>>>(kpm);

    sgemm128<true><<<gg, 256>>>(Cp, Wo, bo, out);
}

// round 3
// speedup vs baseline: 1.4263x; 1.4263x over previous
#include <cuda_runtime.h>
#include <cuda_bf16.h>
#include <math.h>
#include <stdint.h>

#define B_  2
#define S_  2048
#define D_  1024
#define H_  16
#define DK_ 64
#define MROWS (B_*S_)      // 4096

// ---------------- scratch (allocation-free: __device__ globals) -------------
__device__ float g_Q[B_*S_*D_];
__device__ float g_K[B_*S_*D_];
__device__ float g_V[B_*S_*D_];
__device__ float g_ctx[B_*S_*D_];
__device__ float g_vsum[B_*H_*DK_];

__device__ __nv_bfloat16 g_xhi[MROWS*D_];
__device__ __nv_bfloat16 g_xlo[MROWS*D_];
__device__ __nv_bfloat16 g_chi[MROWS*D_];
__device__ __nv_bfloat16 g_clo[MROWS*D_];
__device__ __nv_bfloat16 g_wthi[4*D_*D_];   // transposed weights [N,K], 4 of them
__device__ __nv_bfloat16 g_wtlo[4*D_*D_];

// ======================= helpers =============================================
__device__ __forceinline__ uint32_t smem_u32(const void* p) {
    uint32_t a;
    asm("{ .reg .u64 t; cvta.to.shared.u64 t, %1; cvt.u32.u64 %0, t; }"
        : "=r"(a) : "l"(p));
    return a;
}

__device__ __forceinline__ void ldsm_x4(uint32_t* r, uint32_t addr) {
    asm volatile("ldmatrix.sync.aligned.m8n8.x4.shared.b16 {%0,%1,%2,%3}, [%4];"
                 : "=r"(r[0]), "=r"(r[1]), "=r"(r[2]), "=r"(r[3]) : "r"(addr));
}

__device__ __forceinline__ void mma16816(float* c, const uint32_t* a, const uint32_t* b) {
    asm volatile("mma.sync.aligned.m16n8k16.row.col.f32.bf16.bf16.f32 "
                 "{%0,%1,%2,%3}, {%4,%5,%6,%7}, {%8,%9}, {%0,%1,%2,%3};"
                 : "+f"(c[0]), "+f"(c[1]), "+f"(c[2]), "+f"(c[3])
                 : "r"(a[0]), "r"(a[1]), "r"(a[2]), "r"(a[3]),
                   "r"(b[0]), "r"(b[1]));
}

// ======================= preprocessing kernels ==============================
__global__ void split_kernel(const float* __restrict__ src,
                             __nv_bfloat16* __restrict__ hi,
                             __nv_bfloat16* __restrict__ lo) {
    int i = blockIdx.x * blockDim.x + threadIdx.x;   // float4 index
    float4 v = ((const float4*)src)[i];
    __nv_bfloat16 h0 = __float2bfloat16(v.x), h1 = __float2bfloat16(v.y);
    __nv_bfloat16 h2 = __float2bfloat16(v.z), h3 = __float2bfloat16(v.w);
    __nv_bfloat16 l0 = __float2bfloat16(v.x - __bfloat162float(h0));
    __nv_bfloat16 l1 = __float2bfloat16(v.y - __bfloat162float(h1));
    __nv_bfloat16 l2 = __float2bfloat16(v.z - __bfloat162float(h2));
    __nv_bfloat16 l3 = __float2bfloat16(v.w - __bfloat162float(h3));
    __nv_bfloat162* hp = (__nv_bfloat162*)(hi + 4 * (size_t)i);
    __nv_bfloat162* lp = (__nv_bfloat162*)(lo + 4 * (size_t)i);
    hp[0] = __nv_bfloat162(h0, h1); hp[1] = __nv_bfloat162(h2, h3);
    lp[0] = __nv_bfloat162(l0, l1); lp[1] = __nv_bfloat162(l2, l3);
}

// W[K=1024, N=1024] fp32 -> WT[N, K] bf16 hi/lo
__global__ void transpose_split_kernel(const float* __restrict__ W,
                                       __nv_bfloat16* __restrict__ Thi,
                                       __nv_bfloat16* __restrict__ Tlo) {
    __shared__ float t[32][33];
    const int n0 = blockIdx.x * 32, k0 = blockIdx.y * 32;
    for (int j = threadIdx.y; j < 32; j += 8)
        t[j][threadIdx.x] = W[(size_t)(k0 + j) * D_ + n0 + threadIdx.x];
    __syncthreads();
    for (int j = threadIdx.y; j < 32; j += 8) {
        float v = t[threadIdx.x][j];
        __nv_bfloat16 h = __float2bfloat16(v);
        __nv_bfloat16 l = __float2bfloat16(v - __bfloat162float(h));
        size_t o = (size_t)(n0 + j) * D_ + k0 + threadIdx.x;
        Thi[o] = h; Tlo[o] = l;
    }
}

// ======================= mma.sync bf16x3 GEMM ================================
// C[4096,1024] = A[4096,1024] @ B^T  (B stored [N,K] K-major, hi/lo bf16)
// CTA tile 128x128, warp tile 64x32, K staged 64 per iteration.
#define KC   64
#define SSTR 72              // smem row stride in bf16 elems (144B)
#define GEMM_SMEM (4 * 128 * SSTR * 2)   // 73728 B

template<bool ADD_BIAS>
__global__ void __launch_bounds__(256) mma_gemm(const __nv_bfloat16* __restrict__ Ahi,
                                                const __nv_bfloat16* __restrict__ Alo,
                                                const __nv_bfloat16* __restrict__ Bhi,
                                                const __nv_bfloat16* __restrict__ Blo,
                                                const float* __restrict__ bias,
                                                float* __restrict__ C) {
    extern __shared__ __nv_bfloat16 smb[];
    __nv_bfloat16* As_h = smb;
    __nv_bfloat16* As_l = As_h + 128 * SSTR;
    __nv_bfloat16* Bs_h = As_l + 128 * SSTR;
    __nv_bfloat16* Bs_l = Bs_h + 128 * SSTR;

    const int tid  = threadIdx.x;
    const int lane = tid & 31;
    const int wid  = tid >> 5;
    const int wm   = wid >> 2;           // 0..1
    const int wn   = wid & 3;            // 0..3
    const int rowBase = blockIdx.y * 128;
    const int colBase = blockIdx.x * 128;

    const uint32_t sAh = smem_u32(As_h);
    const uint32_t sAl = smem_u32(As_l);
    const uint32_t sBh = smem_u32(Bs_h);
    const uint32_t sBl = smem_u32(Bs_l);

    // ldmatrix lane geometry
    const int aRow = ((lane & 8) ? 8 : 0) + (lane & 7);   // within 16-row A tile
    const int aK   = ((lane & 16) ? 8 : 0);               // elems
    const int bRow = ((lane & 16) ? 8 : 0) + (lane & 7);  // within 16-row (n) B pair
    const int bK   = ((lane & 8) ? 8 : 0);

    float acc[4][4][4];
    #pragma unroll
    for (int i = 0; i < 4; i++)
        #pragma unroll
        for (int j = 0; j < 4; j++)
            #pragma unroll
            for (int q = 0; q < 4; q++) acc[i][j][q] = 0.f;

    for (int c = 0; c < 16; c++) {
        const int kb = c * KC;
        if (c) __syncthreads();
        // stage A/B (hi+lo) tiles: 128x64 each, uint4 per ld
        #pragma unroll
        for (int u = 0; u < 4; u++) {
            const int idx = u * 256 + tid;
            const int r  = idx >> 3;
            const int cs = (idx & 7) * 8;
            const size_t ga = (size_t)(rowBase + r) * D_ + kb + cs;
            const size_t gb = (size_t)(colBase + r) * D_ + kb + cs;
            const int so = r * SSTR + cs;
            *(uint4*)(As_h + so) = *(const uint4*)(Ahi + ga);
            *(uint4*)(As_l + so) = *(const uint4*)(Alo + ga);
            *(uint4*)(Bs_h + so) = *(const uint4*)(Bhi + gb);
            *(uint4*)(Bs_l + so) = *(const uint4*)(Blo + gb);
        }
        __syncthreads();

        #pragma unroll
        for (int k16 = 0; k16 < 4; k16++) {
            const int kk = k16 * 16;
            // B fragments: 4 n-tiles, hi and lo
            uint32_t bh[4][2], bl[4][2];
            #pragma unroll
            for (int g = 0; g < 2; g++) {
                const uint32_t off =
                    (uint32_t)((wn * 32 + g * 16 + bRow) * SSTR + kk + bK) * 2;
                uint32_t t4[4];
                ldsm_x4(t4, sBh + off);
                bh[2*g][0] = t4[0]; bh[2*g][1] = t4[1];
                bh[2*g+1][0] = t4[2]; bh[2*g+1][1] = t4[3];
                ldsm_x4(t4, sBl + off);
                bl[2*g][0] = t4[0]; bl[2*g][1] = t4[1];
                bl[2*g+1][0] = t4[2]; bl[2*g+1][1] = t4[3];
            }
            #pragma unroll
            for (int mi = 0; mi < 4; mi++) {
                const uint32_t offA =
                    (uint32_t)((wm * 64 + mi * 16 + aRow) * SSTR + kk + aK) * 2;
                uint32_t ah[4], al[4];
                ldsm_x4(ah, sAh + offA);
                ldsm_x4(al, sAl + offA);
                #pragma unroll
                for (int ni = 0; ni < 4; ni++) {
                    mma16816(acc[mi][ni], ah, bh[ni]);
                    mma16816(acc[mi][ni], ah, bl[ni]);
                    mma16816(acc[mi][ni], al, bh[ni]);
                }
            }
        }
    }

    // epilogue
    const int qr = lane >> 2;            // row within 8
    const int qc = (lane & 3) * 2;       // col within 8
    #pragma unroll
    for (int mi = 0; mi < 4; mi++) {
        const int m0 = rowBase + wm * 64 + mi * 16 + qr;
        #pragma unroll
        for (int ni = 0; ni < 4; ni++) {
            const int cc = colBase + wn * 32 + ni * 8 + qc;
            float b0 = 0.f, b1 = 0.f;
            if (ADD_BIAS) { b0 = bias[cc]; b1 = bias[cc + 1]; }
            float2 v0; v0.x = acc[mi][ni][0] + b0; v0.y = acc[mi][ni][1] + b1;
            float2 v1; v1.x = acc[mi][ni][2] + b0; v1.y = acc[mi][ni][3] + b1;
            *(float2*)&C[(size_t)m0 * D_ + cc] = v0;
            *(float2*)&C[(size_t)(m0 + 8) * D_ + cc] = v1;
        }
    }
}

// ---------------- per-(b,h) V row-sum (for fully-masked rows) ---------------
__global__ void vsum_kernel() {
    __shared__ float red[256];
    const int bh = blockIdx.x;
    const int b  = bh / H_, h = bh % H_;
    const int dk = threadIdx.x & 63;
    const int chunk = threadIdx.x >> 6;
    const float* Vg = g_V + (size_t)b * S_ * D_ + h * DK_ + dk;
    float s = 0.f;
    for (int i = chunk * 512; i < (chunk + 1) * 512; i++)
        s += Vg[(size_t)i * D_];
    red[threadIdx.x] = s;
    __syncthreads();
    if (threadIdx.x < 64) {
        float t = red[threadIdx.x] + red[threadIdx.x + 64]
                + red[threadIdx.x + 128] + red[threadIdx.x + 192];
        g_vsum[bh * DK_ + threadIdx.x] = t;
    }
}

// ---------------- flash attention: 64x64 tiles, online softmax --------------
#define FBM  64
#define FBN  64
#define FSTR 65

__device__ __forceinline__ float rmax16(float v) {
    v = fmaxf(v, __shfl_xor_sync(0xffffffffu, v, 1));
    v = fmaxf(v, __shfl_xor_sync(0xffffffffu, v, 2));
    v = fmaxf(v, __shfl_xor_sync(0xffffffffu, v, 4));
    v = fmaxf(v, __shfl_xor_sync(0xffffffffu, v, 8));
    return v;
}
__device__ __forceinline__ float rsum16(float v) {
    v += __shfl_xor_sync(0xffffffffu, v, 1);
    v += __shfl_xor_sync(0xffffffffu, v, 2);
    v += __shfl_xor_sync(0xffffffffu, v, 4);
    v += __shfl_xor_sync(0xffffffffu, v, 8);
    return v;
}

__global__ void __launch_bounds__(256) flash_kernel(const int* __restrict__ kpm) {
    extern __shared__ float smf[];
    float* Qs   = smf;
    float* Ks   = Qs + 64 * FSTR;
    float* Vs   = Ks + 64 * FSTR;
    float* Ps   = Vs + 64 * FSTR;
    float* pads = Ps + 64 * FSTR;

    const int tid = threadIdx.x;
    const int tx  = tid & 15;
    const int ty  = tid >> 4;
    const int qblk = blockIdx.x;
    const int bh   = blockIdx.y;
    const int b = bh / H_, h = bh % H_;

    const float* Qg = g_Q + ((size_t)b * S_ + qblk * FBM) * D_ + h * DK_;
    const float* Kg = g_K + (size_t)b * S_ * D_ + h * DK_;
    const float* Vg = g_V + (size_t)b * S_ * D_ + h * DK_;

    {
        const int r = tid >> 2;
        const int c = (tid & 3) * 16;
        const float* src = Qg + (size_t)r * D_ + c;
        float* dst = Qs + r * FSTR + c;
        #pragma unroll
        for (int u = 0; u < 16; u++) dst[u] = src[u];
    }

    float m_r[4], l_r[4], o_acc[4][4];
    #pragma unroll
    for (int i = 0; i < 4; i++) {
        m_r[i] = -INFINITY; l_r[i] = 0.f;
        #pragma unroll
        for (int c = 0; c < 4; c++) o_acc[i][c] = 0.f;
    }

    const int nkt = qblk + 1;
    const int qrow0 = qblk * FBM + 4 * ty;

    for (int kt = 0; kt < nkt; kt++) {
        __syncthreads();
        {
            const int r = tid >> 2;
            const int c = (tid & 3) * 16;
            const float* ks = Kg + (size_t)(kt * FBN + r) * D_ + c;
            const float* vs = Vg + (size_t)(kt * FBN + r) * D_ + c;
            float* kd = Ks + r * FSTR + c;
            float* vd = Vs + r * FSTR + c;
            #pragma unroll
            for (int u = 0; u < 16; u++) { kd[u] = ks[u]; vd[u] = vs[u]; }
        }
        if (tid < 64) pads[tid] = kpm[b * S_ + kt * FBN + tid] ? 1.f : 0.f;
        __syncthreads();

        float s[4][4] = {};
        #pragma unroll 8
        for (int d = 0; d < 64; d++) {
            float qr[4], kr[4];
            #pragma unroll
            for (int i = 0; i < 4; i++) qr[i] = Qs[(4*ty+i)*FSTR + d];
            #pragma unroll
            for (int j = 0; j < 4; j++) kr[j] = Ks[(4*tx+j)*FSTR + d];
            #pragma unroll
            for (int i = 0; i < 4; i++)
                #pragma unroll
                for (int j = 0; j < 4; j++)
                    s[i][j] = fmaf(qr[i], kr[j], s[i][j]);
        }

        const int kcol0 = kt * FBN + 4 * tx;
        float padj[4];
        #pragma unroll
        for (int j = 0; j < 4; j++) padj[j] = pads[4*tx + j];
        #pragma unroll
        for (int i = 0; i < 4; i++)
            #pragma unroll
            for (int j = 0; j < 4; j++) {
                bool valid = (kcol0 + j <= qrow0 + i) && (padj[j] == 0.f);
                s[i][j] = valid ? s[i][j] * 0.125f : -INFINITY;
            }

        #pragma unroll
        for (int i = 0; i < 4; i++) {
            float mt = fmaxf(fmaxf(s[i][0], s[i][1]), fmaxf(s[i][2], s[i][3]));
            mt = rmax16(mt);
            const float mn = fmaxf(m_r[i], mt);
            float p[4], psum;
            if (mn == -INFINITY) {
                p[0] = p[1] = p[2] = p[3] = 0.f;
                psum = 0.f;
            } else {
                const float alpha = __expf(m_r[i] - mn);
                #pragma unroll
                for (int j = 0; j < 4; j++)
                    p[j] = (s[i][j] == -INFINITY) ? 0.f : __expf(s[i][j] - mn);
                psum = (p[0] + p[1]) + (p[2] + p[3]);
                l_r[i] *= alpha;
                #pragma unroll
                for (int c = 0; c < 4; c++) o_acc[i][c] *= alpha;
            }
            psum = rsum16(psum);
            m_r[i]  = mn;
            l_r[i] += psum;
            #pragma unroll
            for (int j = 0; j < 4; j++)
                Ps[(4*ty+i)*FSTR + 4*tx + j] = p[j];
        }
        __syncthreads();

        #pragma unroll 8
        for (int kk = 0; kk < 64; kk++) {
            float vr[4];
            #pragma unroll
            for (int c = 0; c < 4; c++) vr[c] = Vs[kk * FSTR + 4*tx + c];
            #pragma unroll
            for (int i = 0; i < 4; i++) {
                const float pv = Ps[(4*ty+i)*FSTR + kk];
                #pragma unroll
                for (int c = 0; c < 4; c++)
                    o_acc[i][c] = fmaf(pv, vr[c], o_acc[i][c]);
            }
        }
    }

    const float invS = 1.0f / (float)S_;
    #pragma unroll
    for (int i = 0; i < 4; i++) {
        const bool dead = (m_r[i] == -INFINITY);
        const float inv_l = dead ? 0.f : 1.0f / l_r[i];
        const int q = qrow0 + i;
        float* outp = g_ctx + ((size_t)b * S_ + q) * D_ + h * DK_ + 4 * tx;
        #pragma unroll
        for (int c = 0; c < 4; c++) {
            float val = dead ? g_vsum[bh * DK_ + 4*tx + c] * invS
                             : o_acc[i][c] * inv_l;
            outp[c] = val;
        }
    }
}

// ---------------- launch ------------------------------------------------------
extern "C" void kernel_launch(void* const* d_in, const int* in_sizes, int n_in,
                              void* d_out, int out_size) {
    const float* x   = (const float*)d_in[0];
    const int*   kpm = (const int*)d_in[2];
    const float* Wq  = (const float*)d_in[3];
    const float* Wk  = (const float*)d_in[4];
    const float* Wv  = (const float*)d_in[5];
    const float* Wo  = (const float*)d_in[6];
    const float* bo  = (const float*)d_in[7];
    float* out = (float*)d_out;

    float *Qp, *Kp, *Vp, *Cp;
    __nv_bfloat16 *xhi, *xlo, *chi, *clo, *wthi, *wtlo;
    cudaGetSymbolAddress((void**)&Qp, g_Q);
    cudaGetSymbolAddress((void**)&Kp, g_K);
    cudaGetSymbolAddress((void**)&Vp, g_V);
    cudaGetSymbolAddress((void**)&Cp, g_ctx);
    cudaGetSymbolAddress((void**)&xhi, g_xhi);
    cudaGetSymbolAddress((void**)&xlo, g_xlo);
    cudaGetSymbolAddress((void**)&chi, g_chi);
    cudaGetSymbolAddress((void**)&clo, g_clo);
    cudaGetSymbolAddress((void**)&wthi, g_wthi);
    cudaGetSymbolAddress((void**)&wtlo, g_wtlo);

    cudaFuncSetAttribute(mma_gemm<false>, cudaFuncAttributeMaxDynamicSharedMemorySize, GEMM_SMEM);
    cudaFuncSetAttribute(mma_gemm<true>,  cudaFuncAttributeMaxDynamicSharedMemorySize, GEMM_SMEM);
    const int fsm = (4 * 64 * FSTR + 64) * (int)sizeof(float);
    cudaFuncSetAttribute(flash_kernel, cudaFuncAttributeMaxDynamicSharedMemorySize, fsm);

    // 1) split x into bf16 hi/lo
    split_kernel<<<(MROWS * D_ / 4) / 256, 256>>>(x, xhi, xlo);

    // 2) transpose+split the four weight matrices
    dim3 tb(32, 8), tg(32, 32);
    transpose_split_kernel<<<tg, tb>>>(Wq, wthi + 0 * (size_t)D_ * D_, wtlo + 0 * (size_t)D_ * D_);
    transpose_split_kernel<<<tg, tb>>>(Wk, wthi + 1 * (size_t)D_ * D_, wtlo + 1 * (size_t)D_ * D_);
    transpose_split_kernel<<<tg, tb>>>(Wv, wthi + 2 * (size_t)D_ * D_, wtlo + 2 * (size_t)D_ * D_);
    transpose_split_kernel<<<tg, tb>>>(Wo, wthi + 3 * (size_t)D_ * D_, wtlo + 3 * (size_t)D_ * D_);

    // 3) Q/K/V projections on tensor cores (mma.sync bf16x3)
    dim3 gg(D_ / 128, MROWS / 128);    // (8, 32)
    mma_gemm<false><<<gg, 256, GEMM_SMEM>>>(xhi, xlo, wthi + 0 * (size_t)D_ * D_, wtlo + 0 * (size_t)D_ * D_, nullptr, Qp);
    mma_gemm<false><<<gg, 256, GEMM_SMEM>>>(xhi, xlo, wthi + 1 * (size_t)D_ * D_, wtlo + 1 * (size_t)D_ * D_, nullptr, Kp);
    mma_gemm<false><<<gg, 256, GEMM_SMEM>>>(xhi, xlo, wthi + 2 * (size_t)D_ * D_, wtlo + 2 * (size_t)D_ * D_, nullptr, Vp);

    // 4) V row-sums for fully-masked rows
    vsum_kernel<<<B_ * H_, 256>>>();

    // 5) flash attention (fp32)
    dim3 fg(S_ / FBM, B_ * H_);
    flash_kernel<<<fg, 256, fsm>>>(kpm);

    // 6) split ctx, output projection with bias
    split_kernel<<<(MROWS * D_ / 4) / 256, 256>>>(Cp, chi, clo);
    mma_gemm<true><<<gg, 256, GEMM_SMEM>>>(chi, clo, wthi + 3 * (size_t)D_ * D_, wtlo + 3 * (size_t)D_ * D_, bo, out);
}

// round 4
// speedup vs baseline: 3.3454x; 2.3456x over previous
#include <cuda_runtime.h>
#include <cuda_bf16.h>
#include <math.h>
#include <stdint.h>

#define B_  2
#define S_  2048
#define D_  1024
#define H_  16
#define DK_ 64
#define MROWS (B_*S_)      // 4096

// ---------------- scratch (allocation-free: __device__ globals) -------------
__device__ __nv_bfloat16 g_qh[MROWS*D_];
__device__ __nv_bfloat16 g_ql[MROWS*D_];
__device__ __nv_bfloat16 g_kh[MROWS*D_];
__device__ __nv_bfloat16 g_kl[MROWS*D_];
__device__ __nv_bfloat16 g_vh[MROWS*D_];
__device__ __nv_bfloat16 g_vl[MROWS*D_];
__device__ __nv_bfloat16 g_chi[MROWS*D_];
__device__ __nv_bfloat16 g_clo[MROWS*D_];
__device__ __nv_bfloat16 g_xhi[MROWS*D_];
__device__ __nv_bfloat16 g_xlo[MROWS*D_];
__device__ __nv_bfloat16 g_wthi[4*D_*D_];   // transposed weights [N,K]
__device__ __nv_bfloat16 g_wtlo[4*D_*D_];
__device__ float g_vsum[B_*H_*DK_];

// ======================= helpers =============================================
__device__ __forceinline__ uint32_t smem_u32(const void* p) {
    uint32_t a;
    asm("{ .reg .u64 t; cvta.to.shared.u64 t, %1; cvt.u32.u64 %0, t; }"
        : "=r"(a) : "l"(p));
    return a;
}
__device__ __forceinline__ void ldsm_x4(uint32_t* r, uint32_t addr) {
    asm volatile("ldmatrix.sync.aligned.m8n8.x4.shared.b16 {%0,%1,%2,%3}, [%4];"
                 : "=r"(r[0]), "=r"(r[1]), "=r"(r[2]), "=r"(r[3]) : "r"(addr));
}
__device__ __forceinline__ void ldsm_x4_t(uint32_t* r, uint32_t addr) {
    asm volatile("ldmatrix.sync.aligned.m8n8.x4.trans.shared.b16 {%0,%1,%2,%3}, [%4];"
                 : "=r"(r[0]), "=r"(r[1]), "=r"(r[2]), "=r"(r[3]) : "r"(addr));
}
__device__ __forceinline__ void mma16816(float* c, const uint32_t* a, const uint32_t* b) {
    asm volatile("mma.sync.aligned.m16n8k16.row.col.f32.bf16.bf16.f32 "
                 "{%0,%1,%2,%3}, {%4,%5,%6,%7}, {%8,%9}, {%0,%1,%2,%3};"
                 : "+f"(c[0]), "+f"(c[1]), "+f"(c[2]), "+f"(c[3])
                 : "r"(a[0]), "r"(a[1]), "r"(a[2]), "r"(a[3]),
                   "r"(b[0]), "r"(b[1]));
}
__device__ __forceinline__ uint32_t pack_bf16x2(float a, float b) {
    __nv_bfloat162 t = __floats2bfloat162_rn(a, b);
    return *(uint32_t*)&t;
}

// ======================= preprocessing kernels ==============================
__global__ void split_kernel(const float* __restrict__ src,
                             __nv_bfloat16* __restrict__ hi,
                             __nv_bfloat16* __restrict__ lo) {
    int i = blockIdx.x * blockDim.x + threadIdx.x;
    float4 v = ((const float4*)src)[i];
    __nv_bfloat16 h0 = __float2bfloat16(v.x), h1 = __float2bfloat16(v.y);
    __nv_bfloat16 h2 = __float2bfloat16(v.z), h3 = __float2bfloat16(v.w);
    __nv_bfloat16 l0 = __float2bfloat16(v.x - __bfloat162float(h0));
    __nv_bfloat16 l1 = __float2bfloat16(v.y - __bfloat162float(h1));
    __nv_bfloat16 l2 = __float2bfloat16(v.z - __bfloat162float(h2));
    __nv_bfloat16 l3 = __float2bfloat16(v.w - __bfloat162float(h3));
    __nv_bfloat162* hp = (__nv_bfloat162*)(hi + 4 * (size_t)i);
    __nv_bfloat162* lp = (__nv_bfloat162*)(lo + 4 * (size_t)i);
    hp[0] = __nv_bfloat162(h0, h1); hp[1] = __nv_bfloat162(h2, h3);
    lp[0] = __nv_bfloat162(l0, l1); lp[1] = __nv_bfloat162(l2, l3);
}

__global__ void transpose_split_kernel(const float* __restrict__ W,
                                       __nv_bfloat16* __restrict__ Thi,
                                       __nv_bfloat16* __restrict__ Tlo) {
    __shared__ float t[32][33];
    const int n0 = blockIdx.x * 32, k0 = blockIdx.y * 32;
    for (int j = threadIdx.y; j < 32; j += 8)
        t[j][threadIdx.x] = W[(size_t)(k0 + j) * D_ + n0 + threadIdx.x];
    __syncthreads();
    for (int j = threadIdx.y; j < 32; j += 8) {
        float v = t[threadIdx.x][j];
        __nv_bfloat16 h = __float2bfloat16(v);
        __nv_bfloat16 l = __float2bfloat16(v - __bfloat162float(h));
        size_t o = (size_t)(n0 + j) * D_ + k0 + threadIdx.x;
        Thi[o] = h; Tlo[o] = l;
    }
}

// ======================= mma.sync bf16x3 GEMM ================================
#define KC   64
#define SSTR 72
#define GEMM_SMEM (4 * 128 * SSTR * 2)

template<bool SPLIT_OUT>
__global__ void __launch_bounds__(256) mma_gemm(const __nv_bfloat16* __restrict__ Ahi,
                                                const __nv_bfloat16* __restrict__ Alo,
                                                const __nv_bfloat16* __restrict__ Bhi,
                                                const __nv_bfloat16* __restrict__ Blo,
                                                const float* __restrict__ bias,
                                                float* __restrict__ C,
                                                __nv_bfloat16* __restrict__ Chi,
                                                __nv_bfloat16* __restrict__ Clo) {
    extern __shared__ __nv_bfloat16 smb[];
    __nv_bfloat16* As_h = smb;
    __nv_bfloat16* As_l = As_h + 128 * SSTR;
    __nv_bfloat16* Bs_h = As_l + 128 * SSTR;
    __nv_bfloat16* Bs_l = Bs_h + 128 * SSTR;

    const int tid  = threadIdx.x;
    const int lane = tid & 31;
    const int wid  = tid >> 5;
    const int wm   = wid >> 2;
    const int wn   = wid & 3;
    const int rowBase = blockIdx.y * 128;
    const int colBase = blockIdx.x * 128;

    const uint32_t sAh = smem_u32(As_h);
    const uint32_t sAl = smem_u32(As_l);
    const uint32_t sBh = smem_u32(Bs_h);
    const uint32_t sBl = smem_u32(Bs_l);

    const int aRow = ((lane & 8) ? 8 : 0) + (lane & 7);
    const int aK   = ((lane & 16) ? 8 : 0);
    const int bRow = ((lane & 16) ? 8 : 0) + (lane & 7);
    const int bK   = ((lane & 8) ? 8 : 0);

    float acc[4][4][4];
    #pragma unroll
    for (int i = 0; i < 4; i++)
        #pragma unroll
        for (int j = 0; j < 4; j++)
            #pragma unroll
            for (int q = 0; q < 4; q++) acc[i][j][q] = 0.f;

    for (int c = 0; c < 16; c++) {
        const int kb = c * KC;
        if (c) __syncthreads();
        #pragma unroll
        for (int u = 0; u < 4; u++) {
            const int idx = u * 256 + tid;
            const int r  = idx >> 3;
            const int cs = (idx & 7) * 8;
            const size_t ga = (size_t)(rowBase + r) * D_ + kb + cs;
            const size_t gb = (size_t)(colBase + r) * D_ + kb + cs;
            const int so = r * SSTR + cs;
            *(uint4*)(As_h + so) = *(const uint4*)(Ahi + ga);
            *(uint4*)(As_l + so) = *(const uint4*)(Alo + ga);
            *(uint4*)(Bs_h + so) = *(const uint4*)(Bhi + gb);
            *(uint4*)(Bs_l + so) = *(const uint4*)(Blo + gb);
        }
        __syncthreads();

        #pragma unroll
        for (int k16 = 0; k16 < 4; k16++) {
            const int kk = k16 * 16;
            uint32_t bh[4][2], bl[4][2];
            #pragma unroll
            for (int g = 0; g < 2; g++) {
                const uint32_t off =
                    (uint32_t)((wn * 32 + g * 16 + bRow) * SSTR + kk + bK) * 2;
                uint32_t t4[4];
                ldsm_x4(t4, sBh + off);
                bh[2*g][0] = t4[0]; bh[2*g][1] = t4[1];
                bh[2*g+1][0] = t4[2]; bh[2*g+1][1] = t4[3];
                ldsm_x4(t4, sBl + off);
                bl[2*g][0] = t4[0]; bl[2*g][1] = t4[1];
                bl[2*g+1][0] = t4[2]; bl[2*g+1][1] = t4[3];
            }
            #pragma unroll
            for (int mi = 0; mi < 4; mi++) {
                const uint32_t offA =
                    (uint32_t)((wm * 64 + mi * 16 + aRow) * SSTR + kk + aK) * 2;
                uint32_t ah[4], al[4];
                ldsm_x4(ah, sAh + offA);
                ldsm_x4(al, sAl + offA);
                #pragma unroll
                for (int ni = 0; ni < 4; ni++) {
                    mma16816(acc[mi][ni], ah, bh[ni]);
                    mma16816(acc[mi][ni], ah, bl[ni]);
                    mma16816(acc[mi][ni], al, bh[ni]);
                }
            }
        }
    }

    const int qr = lane >> 2;
    const int qc = (lane & 3) * 2;
    #pragma unroll
    for (int mi = 0; mi < 4; mi++) {
        const int m0 = rowBase + wm * 64 + mi * 16 + qr;
        #pragma unroll
        for (int ni = 0; ni < 4; ni++) {
            const int cc = colBase + wn * 32 + ni * 8 + qc;
            if (SPLIT_OUT) {
                #pragma unroll
                for (int rr = 0; rr < 2; rr++) {
                    const float f0 = acc[mi][ni][rr*2+0];
                    const float f1 = acc[mi][ni][rr*2+1];
                    __nv_bfloat16 h0 = __float2bfloat16(f0);
                    __nv_bfloat16 h1 = __float2bfloat16(f1);
                    __nv_bfloat16 l0 = __float2bfloat16(f0 - __bfloat162float(h0));
                    __nv_bfloat16 l1 = __float2bfloat16(f1 - __bfloat162float(h1));
                    const size_t o = (size_t)(m0 + rr * 8) * D_ + cc;
                    *(__nv_bfloat162*)(Chi + o) = __nv_bfloat162(h0, h1);
                    *(__nv_bfloat162*)(Clo + o) = __nv_bfloat162(l0, l1);
                }
            } else {
                float b0 = bias[cc], b1 = bias[cc + 1];
                float2 v0; v0.x = acc[mi][ni][0] + b0; v0.y = acc[mi][ni][1] + b1;
                float2 v1; v1.x = acc[mi][ni][2] + b0; v1.y = acc[mi][ni][3] + b1;
                *(float2*)&C[(size_t)m0 * D_ + cc] = v0;
                *(float2*)&C[(size_t)(m0 + 8) * D_ + cc] = v1;
            }
        }
    }
}

// ---------------- per-(b,h) V row-sum (from hi+lo) --------------------------
__global__ void vsum_kernel() {
    __shared__ float red[256];
    const int bh = blockIdx.x;
    const int b  = bh / H_, h = bh % H_;
    const int dk = threadIdx.x & 63;
    const int chunk = threadIdx.x >> 6;
    const __nv_bfloat16* Vh = g_vh + (size_t)b * S_ * D_ + h * DK_ + dk;
    const __nv_bfloat16* Vl = g_vl + (size_t)b * S_ * D_ + h * DK_ + dk;
    float s = 0.f;
    for (int i = chunk * 512; i < (chunk + 1) * 512; i++)
        s += __bfloat162float(Vh[(size_t)i * D_]) + __bfloat162float(Vl[(size_t)i * D_]);
    red[threadIdx.x] = s;
    __syncthreads();
    if (threadIdx.x < 64) {
        float t = red[threadIdx.x] + red[threadIdx.x + 64]
                + red[threadIdx.x + 128] + red[threadIdx.x + 192];
        g_vsum[bh * DK_ + threadIdx.x] = t;
    }
}

// ================= flash attention on mma.sync (bf16x3) ======================
// CTA: 64 q-rows, 128 threads (4 warps x 16 rows). K-tiles of 64 keys.
#define FS 72
#define FLASH_SMEM (6 * 64 * FS * 2 + 64 * 4)

__global__ void __launch_bounds__(128) flash_mma(const int* __restrict__ kpm) {
    extern __shared__ __nv_bfloat16 fsm[];
    __nv_bfloat16* Qh = fsm;
    __nv_bfloat16* Ql = Qh + 64 * FS;
    __nv_bfloat16* Kh = Ql + 64 * FS;
    __nv_bfloat16* Kl = Kh + 64 * FS;
    __nv_bfloat16* Vh = Kl + 64 * FS;
    __nv_bfloat16* Vl = Vh + 64 * FS;
    int* pads = (int*)(Vl + 64 * FS);

    const int tid  = threadIdx.x;
    const int lane = tid & 31;
    const int wq   = tid >> 5;                   // warp q-slice 0..3
    const int qblk = (int)gridDim.x - 1 - (int)blockIdx.x;   // big tiles first
    const int bh   = blockIdx.y;
    const int b = bh / H_, h = bh % H_;

    const uint32_t sQh = smem_u32(Qh), sQl = smem_u32(Ql);
    const uint32_t sKh = smem_u32(Kh), sKl = smem_u32(Kl);
    const uint32_t sVh = smem_u32(Vh), sVl = smem_u32(Vl);

    const size_t headOff = (size_t)b * S_ * D_ + h * DK_;
    const size_t qOff = headOff + (size_t)(qblk * 64) * D_;

    // load Q tile (64x64 bf16 hi/lo)
    #pragma unroll
    for (int u = 0; u < 4; u++) {
        const int idx = u * 128 + tid;
        const int r = idx >> 3, c = (idx & 7) * 8;
        *(uint4*)(Qh + r * FS + c) = *(const uint4*)(g_qh + qOff + (size_t)r * D_ + c);
        *(uint4*)(Ql + r * FS + c) = *(const uint4*)(g_ql + qOff + (size_t)r * D_ + c);
    }

    // ldmatrix lane geometry
    const int aRow = ((lane & 8) ? 8 : 0) + (lane & 7);
    const int aK   = ((lane & 16) ? 8 : 0);
    const int bRow = ((lane & 16) ? 8 : 0) + (lane & 7);
    const int bK   = ((lane & 8) ? 8 : 0);
    const int vRow = ((lane & 8) ? 8 : 0) + (lane & 7);
    const int vCol = ((lane & 16) ? 8 : 0);

    float m0 = -INFINITY, m1 = -INFINITY, l0 = 0.f, l1 = 0.f;
    float oacc[8][4];
    #pragma unroll
    for (int ni = 0; ni < 8; ni++)
        #pragma unroll
        for (int q = 0; q < 4; q++) oacc[ni][q] = 0.f;

    const int qr0 = qblk * 64 + wq * 16 + (lane >> 2);  // global q row (row 0)
    const int qr1 = qr0 + 8;
    const int colq = (lane & 3) * 2;                    // col pair within n8

    for (int kt = 0; kt <= qblk; kt++) {
        __syncthreads();
        {
            const size_t kOff = headOff + (size_t)(kt * 64) * D_;
            #pragma unroll
            for (int u = 0; u < 4; u++) {
                const int idx = u * 128 + tid;
                const int r = idx >> 3, c = (idx & 7) * 8;
                const size_t go = kOff + (size_t)r * D_ + c;
                const int so = r * FS + c;
                *(uint4*)(Kh + so) = *(const uint4*)(g_kh + go);
                *(uint4*)(Kl + so) = *(const uint4*)(g_kl + go);
                *(uint4*)(Vh + so) = *(const uint4*)(g_vh + go);
                *(uint4*)(Vl + so) = *(const uint4*)(g_vl + go);
            }
            if (tid < 64) pads[tid] = kpm[b * S_ + kt * 64 + tid];
        }
        __syncthreads();

        // ---- S = Q @ K^T (bf16x3) ----
        float sacc[8][4];
        #pragma unroll
        for (int ni = 0; ni < 8; ni++)
            #pragma unroll
            for (int q = 0; q < 4; q++) sacc[ni][q] = 0.f;

        #pragma unroll
        for (int j = 0; j < 4; j++) {
            const int kk = j * 16;
            uint32_t ah[4], al[4];
            ldsm_x4(ah, sQh + (uint32_t)((wq * 16 + aRow) * FS + kk + aK) * 2);
            ldsm_x4(al, sQl + (uint32_t)((wq * 16 + aRow) * FS + kk + aK) * 2);
            #pragma unroll
            for (int g = 0; g < 4; g++) {
                const uint32_t off = (uint32_t)((g * 16 + bRow) * FS + kk + bK) * 2;
                uint32_t th[4], tl[4];
                ldsm_x4(th, sKh + off);
                ldsm_x4(tl, sKl + off);
                mma16816(sacc[2*g],   ah, th);     // th[0..1]
                mma16816(sacc[2*g],   ah, tl);
                mma16816(sacc[2*g],   al, th);
                mma16816(sacc[2*g+1], ah, th + 2);
                mma16816(sacc[2*g+1], ah, tl + 2);
                mma16816(sacc[2*g+1], al, th + 2);
            }
        }

        // ---- mask + scale ----
        const bool diag = (kt == qblk);
        #pragma unroll
        for (int ni = 0; ni < 8; ni++) {
            const int kc = kt * 64 + ni * 8 + colq;
            const int p0 = pads[ni * 8 + colq];
            const int p1 = pads[ni * 8 + colq + 1];
            bool v00 = !p0, v01 = !p1, v10 = !p0, v11 = !p1;
            if (diag) {
                v00 = v00 && (kc     <= qr0);
                v01 = v01 && (kc + 1 <= qr0);
                v10 = v10 && (kc     <= qr1);
                v11 = v11 && (kc + 1 <= qr1);
            }
            sacc[ni][0] = v00 ? sacc[ni][0] * 0.125f : -INFINITY;
            sacc[ni][1] = v01 ? sacc[ni][1] * 0.125f : -INFINITY;
            sacc[ni][2] = v10 ? sacc[ni][2] * 0.125f : -INFINITY;
            sacc[ni][3] = v11 ? sacc[ni][3] * 0.125f : -INFINITY;
        }

        // ---- online softmax (2 rows per thread, quad reductions) ----
        float mt0 = -INFINITY, mt1 = -INFINITY;
        #pragma unroll
        for (int ni = 0; ni < 8; ni++) {
            mt0 = fmaxf(mt0, fmaxf(sacc[ni][0], sacc[ni][1]));
            mt1 = fmaxf(mt1, fmaxf(sacc[ni][2], sacc[ni][3]));
        }
        mt0 = fmaxf(mt0, __shfl_xor_sync(0xffffffffu, mt0, 1));
        mt0 = fmaxf(mt0, __shfl_xor_sync(0xffffffffu, mt0, 2));
        mt1 = fmaxf(mt1, __shfl_xor_sync(0xffffffffu, mt1, 1));
        mt1 = fmaxf(mt1, __shfl_xor_sync(0xffffffffu, mt1, 2));

        const float mn0 = fmaxf(m0, mt0);
        const float mn1 = fmaxf(m1, mt1);
        const bool live0 = (mn0 != -INFINITY);
        const bool live1 = (mn1 != -INFINITY);
        const float alpha0 = live0 ? __expf(m0 - mn0) : 1.f;
        const float alpha1 = live1 ? __expf(m1 - mn1) : 1.f;

        float ps0 = 0.f, ps1 = 0.f;
        #pragma unroll
        for (int ni = 0; ni < 8; ni++) {
            float p00 = live0 ? __expf(sacc[ni][0] - mn0) : 0.f;
            float p01 = live0 ? __expf(sacc[ni][1] - mn0) : 0.f;
            float p10 = live1 ? __expf(sacc[ni][2] - mn1) : 0.f;
            float p11 = live1 ? __expf(sacc[ni][3] - mn1) : 0.f;
            sacc[ni][0] = p00; sacc[ni][1] = p01;
            sacc[ni][2] = p10; sacc[ni][3] = p11;
            ps0 += p00 + p01;
            ps1 += p10 + p11;
        }
        ps0 += __shfl_xor_sync(0xffffffffu, ps0, 1);
        ps0 += __shfl_xor_sync(0xffffffffu, ps0, 2);
        ps1 += __shfl_xor_sync(0xffffffffu, ps1, 1);
        ps1 += __shfl_xor_sync(0xffffffffu, ps1, 2);

        l0 = l0 * alpha0 + ps0;
        l1 = l1 * alpha1 + ps1;
        m0 = mn0; m1 = mn1;
        #pragma unroll
        for (int ni = 0; ni < 8; ni++) {
            oacc[ni][0] *= alpha0; oacc[ni][1] *= alpha0;
            oacc[ni][2] *= alpha1; oacc[ni][3] *= alpha1;
        }

        // ---- O += P @ V (bf16x3, V via ldmatrix.trans) ----
        #pragma unroll
        for (int j = 0; j < 4; j++) {          // key k16 step
            uint32_t pah[4], pal[4];
            #pragma unroll
            for (int t = 0; t < 2; t++) {      // s-tile 2j+t
                const float f0 = sacc[2*j+t][0], f1 = sacc[2*j+t][1];
                const float f2 = sacc[2*j+t][2], f3 = sacc[2*j+t][3];
                const uint32_t h01 = pack_bf16x2(f0, f1);
                const uint32_t h23 = pack_bf16x2(f2, f3);
                __nv_bfloat162 hb01 = *(__nv_bfloat162*)&h01;
                __nv_bfloat162 hb23 = *(__nv_bfloat162*)&h23;
                pah[2*t]   = h01;
                pah[2*t+1] = h23;
                pal[2*t]   = pack_bf16x2(f0 - __bfloat162float(hb01.x),
                                          f1 - __bfloat162float(hb01.y));
                pal[2*t+1] = pack_bf16x2(f2 - __bfloat162float(hb23.x),
                                          f3 - __bfloat162float(hb23.y));
            }
            // note: pah/pal index order is a0,a1 (tile 2j), a2,a3 (tile 2j+1)
            uint32_t af_h[4] = {pah[0], pah[1], pah[2], pah[3]};
            uint32_t af_l[4] = {pal[0], pal[1], pal[2], pal[3]};
            #pragma unroll
            for (int g = 0; g < 4; g++) {      // dk 16-wide group
                const uint32_t off =
                    (uint32_t)((j * 16 + vRow) * FS + g * 16 + vCol) * 2;
                uint32_t vbh[4], vbl[4];
                ldsm_x4_t(vbh, sVh + off);
                ldsm_x4_t(vbl, sVl + off);
                mma16816(oacc[2*g],   af_h, vbh);
                mma16816(oacc[2*g],   af_h, vbl);
                mma16816(oacc[2*g],   af_l, vbh);
                mma16816(oacc[2*g+1], af_h, vbh + 2);
                mma16816(oacc[2*g+1], af_h, vbl + 2);
                mma16816(oacc[2*g+1], af_l, vbh + 2);
            }
        }
    }

    // ---- epilogue: normalize (or vsum/S for dead rows), write bf16 hi/lo ----
    const float invS = 1.0f / (float)S_;
    const bool dead0 = (m0 == -INFINITY);
    const bool dead1 = (m1 == -INFINITY);
    const float inv0 = dead0 ? 0.f : 1.0f / l0;
    const float inv1 = dead1 ? 0.f : 1.0f / l1;
    const size_t row0 = (size_t)b * S_ + qr0;
    const size_t row1 = (size_t)b * S_ + qr1;
    #pragma unroll
    for (int ni = 0; ni < 8; ni++) {
        const int dd = ni * 8 + colq;
        float v00, v01, v10, v11;
        if (dead0) {
            v00 = g_vsum[bh * DK_ + dd] * invS;
            v01 = g_vsum[bh * DK_ + dd + 1] * invS;
        } else { v00 = oacc[ni][0] * inv0; v01 = oacc[ni][1] * inv0; }
        if (dead1) {
            v10 = g_vsum[bh * DK_ + dd] * invS;
            v11 = g_vsum[bh * DK_ + dd + 1] * invS;
        } else { v10 = oacc[ni][2] * inv1; v11 = oacc[ni][3] * inv1; }

        __nv_bfloat16 h00 = __float2bfloat16(v00), h01 = __float2bfloat16(v01);
        __nv_bfloat16 h10 = __float2bfloat16(v10), h11 = __float2bfloat16(v11);
        const size_t o0 = row0 * D_ + h * DK_ + dd;
        const size_t o1 = row1 * D_ + h * DK_ + dd;
        *(__nv_bfloat162*)(g_chi + o0) = __nv_bfloat162(h00, h01);
        *(__nv_bfloat162*)(g_chi + o1) = __nv_bfloat162(h10, h11);
        *(__nv_bfloat162*)(g_clo + o0) =
            __nv_bfloat162(__float2bfloat16(v00 - __bfloat162float(h00)),
                           __float2bfloat16(v01 - __bfloat162float(h01)));
        *(__nv_bfloat162*)(g_clo + o1) =
            __nv_bfloat162(__float2bfloat16(v10 - __bfloat162float(h10)),
                           __float2bfloat16(v11 - __bfloat162float(h11)));
    }
}

// ---------------- launch ------------------------------------------------------
extern "C" void kernel_launch(void* const* d_in, const int* in_sizes, int n_in,
                              void* d_out, int out_size) {
    const float* x   = (const float*)d_in[0];
    const int*   kpm = (const int*)d_in[2];
    const float* Wq  = (const float*)d_in[3];
    const float* Wk  = (const float*)d_in[4];
    const float* Wv  = (const float*)d_in[5];
    const float* Wo  = (const float*)d_in[6];
    const float* bo  = (const float*)d_in[7];
    float* out = (float*)d_out;

    __nv_bfloat16 *xhi, *xlo, *wthi, *wtlo;
    __nv_bfloat16 *qh, *ql, *kh, *kl, *vh, *vl, *chi, *clo;
    cudaGetSymbolAddress((void**)&xhi, g_xhi);
    cudaGetSymbolAddress((void**)&xlo, g_xlo);
    cudaGetSymbolAddress((void**)&wthi, g_wthi);
    cudaGetSymbolAddress((void**)&wtlo, g_wtlo);
    cudaGetSymbolAddress((void**)&qh, g_qh);
    cudaGetSymbolAddress((void**)&ql, g_ql);
    cudaGetSymbolAddress((void**)&kh, g_kh);
    cudaGetSymbolAddress((void**)&kl, g_kl);
    cudaGetSymbolAddress((void**)&vh, g_vh);
    cudaGetSymbolAddress((void**)&vl, g_vl);
    cudaGetSymbolAddress((void**)&chi, g_chi);
    cudaGetSymbolAddress((void**)&clo, g_clo);

    cudaFuncSetAttribute(mma_gemm<false>, cudaFuncAttributeMaxDynamicSharedMemorySize, GEMM_SMEM);
    cudaFuncSetAttribute(mma_gemm<true>,  cudaFuncAttributeMaxDynamicSharedMemorySize, GEMM_SMEM);
    cudaFuncSetAttribute(flash_mma, cudaFuncAttributeMaxDynamicSharedMemorySize, FLASH_SMEM);

    // 1) split x
    split_kernel<<<(MROWS * D_ / 4) / 256, 256>>>(x, xhi, xlo);

    // 2) transpose+split weights
    dim3 tb(32, 8), tg(32, 32);
    transpose_split_kernel<<<tg, tb>>>(Wq, wthi + 0 * (size_t)D_ * D_, wtlo + 0 * (size_t)D_ * D_);
    transpose_split_kernel<<<tg, tb>>>(Wk, wthi + 1 * (size_t)D_ * D_, wtlo + 1 * (size_t)D_ * D_);
    transpose_split_kernel<<<tg, tb>>>(Wv, wthi + 2 * (size_t)D_ * D_, wtlo + 2 * (size_t)D_ * D_);
    transpose_split_kernel<<<tg, tb>>>(Wo, wthi + 3 * (size_t)D_ * D_, wtlo + 3 * (size_t)D_ * D_);

    // 3) projections -> bf16 hi/lo directly
    dim3 gg(D_ / 128, MROWS / 128);
    mma_gemm<true><<<gg, 256, GEMM_SMEM>>>(xhi, xlo, wthi + 0 * (size_t)D_ * D_, wtlo + 0 * (size_t)D_ * D_, nullptr, nullptr, qh, ql);
    mma_gemm<true><<<gg, 256, GEMM_SMEM>>>(xhi, xlo, wthi + 1 * (size_t)D_ * D_, wtlo + 1 * (size_t)D_ * D_, nullptr, nullptr, kh, kl);
    mma_gemm<true><<<gg, 256, GEMM_SMEM>>>(xhi, xlo, wthi + 2 * (size_t)D_ * D_, wtlo + 2 * (size_t)D_ * D_, nullptr, nullptr, vh, vl);

    // 4) V row-sums
    vsum_kernel<<<B_ * H_, 256>>>();

    // 5) flash attention on tensor cores
    dim3 fg(S_ / 64, B_ * H_);
    flash_mma<<<fg, 128, FLASH_SMEM>>>(kpm);

    // 6) output projection with bias (fp32 out)
    mma_gemm<false><<<gg, 256, GEMM_SMEM>>>(chi, clo, wthi + 3 * (size_t)D_ * D_, wtlo + 3 * (size_t)D_ * D_, bo, out, nullptr, nullptr);
}